// round 7
// baseline (speedup 1.0000x reference)
#include <cuda_runtime.h>

#define NROWS (256 * 32 * 32)   // 262144
#define D 64
#define K 1024
#define KC 128                   // codes per smem chunk
#define SROW 68                  // padded row stride (floats): 272B = 17*16B, aligned for 128b LDS

__device__ float g_embT[K * D];  // code-major codebook [k][d]
__device__ float g_sqe[K];       // ||e_k||^2
__device__ int   g_idx[NROWS];   // argmin index per row
__device__ double g_acc;         // sum of squared (q - x)

__device__ __forceinline__ void ffma2(unsigned long long &c, unsigned long long a, unsigned long long b) {
    asm("fma.rn.f32x2 %0, %1, %2, %0;" : "+l"(c) : "l"(a), "l"(b));
}
__device__ __forceinline__ unsigned long long fadd2(unsigned long long a, unsigned long long b) {
    unsigned long long r;
    asm("add.rn.f32x2 %0, %1, %2;" : "=l"(r) : "l"(a), "l"(b));
    return r;
}

// Transpose codebook, precompute ||e_k||^2, zero the loss accumulator.
// Runs every replay -> deterministic graph.
__global__ void vq_init_kernel(const float* __restrict__ emb) {
    int i = blockIdx.x * blockDim.x + threadIdx.x;
    if (i == 0) g_acc = 0.0;
    if (i < K * D) {
        int d = i >> 10;        // emb is [d][k], i = d*1024 + k
        int k = i & (K - 1);
        g_embT[k * D + d] = emb[i];
    }
    if (i < K) {
        float s = 0.f;
        #pragma unroll 8
        for (int d = 0; d < D; d++) {
            float v = emb[d * K + i];
            s = fmaf(v, v, s);
        }
        g_sqe[i] = s;
    }
}

// One row per thread. Fast fp32 (packed f32x2) scoring s_k = ||e_k||^2 - 2 x.e_k,
// tracking top-2. Near-ties (fast gap < 1e-3) are resolved by BIT-EXACT emulation
// of the reference's fp32 arithmetic (hypothesis H1, XLA CPU on aarch64/NEON):
//   dist_k = fl( fl(A + B_k) - fl(2*dot_k) )
//   A     = rowsum(x*x): 4 NEON lanes, lane j = fmla chain over x[4i+j]^2
//           (i ascending), horizontal fold faddp-style: (l0+l1)+(l2+l3)
//   B_k   = colsum(e*e): sequential over d (axis-0 reduce vectorizes over k,
//           per-k accumulation is a sequential fmla chain)
//   dot_k = Eigen gebp: sequential fmla over d ascending
// Reference argmin scans ascending with strict '<' => pick hi iff dist_hi < dist_lo.
__global__ void __launch_bounds__(256, 2) vq_argmin_kernel(const float* __restrict__ x) {
    __shared__ float sE[KC * SROW];
    __shared__ float sSq[KC];
    int row = blockIdx.x * 256 + threadIdx.x;

    unsigned long long xr[32];  // 64 floats as 32 packed f32x2
    {
        const ulonglong2* xp = reinterpret_cast<const ulonglong2*>(x + (size_t)row * D);
        #pragma unroll
        for (int i = 0; i < 16; i++) {
            ulonglong2 v = xp[i];
            xr[2 * i]     = v.x;
            xr[2 * i + 1] = v.y;
        }
    }

    float best  = 3.0e38f;  int bidx  = 0;
    float best2 = 3.0e38f;  int bidx2 = 0;

    for (int c0 = 0; c0 < K; c0 += KC) {
        __syncthreads();
        // coalesced fill from code-major codebook; conflict-free smem writes
        #pragma unroll
        for (int i = threadIdx.x; i < KC * D; i += 256) {
            int kc = i >> 6;
            int d  = i & 63;
            sE[kc * SROW + d] = g_embT[(c0 + kc) * D + d];
        }
        if (threadIdx.x < KC) sSq[threadIdx.x] = g_sqe[c0 + threadIdx.x];
        __syncthreads();

        for (int kc = 0; kc < KC; kc++) {
            const ulonglong2* ep = reinterpret_cast<const ulonglong2*>(&sE[kc * SROW]);
            unsigned long long a0 = 0ull, a1 = 0ull, a2 = 0ull, a3 = 0ull;
            #pragma unroll
            for (int i = 0; i < 16; i += 2) {
                ulonglong2 e0 = ep[i];
                ulonglong2 e1 = ep[i + 1];
                ffma2(a0, xr[2 * i],     e0.x);
                ffma2(a1, xr[2 * i + 1], e0.y);
                ffma2(a2, xr[2 * i + 2], e1.x);
                ffma2(a3, xr[2 * i + 3], e1.y);
            }
            unsigned long long s = fadd2(fadd2(a0, a1), fadd2(a2, a3));
            float dot = __uint_as_float((unsigned)s) + __uint_as_float((unsigned)(s >> 32));
            float val = fmaf(dot, -2.0f, sSq[kc]);
            if (val < best) {
                best2 = best; bidx2 = bidx;
                best  = val;  bidx  = c0 + kc;
            } else if (val < best2) {
                best2 = val;  bidx2 = c0 + kc;
            }
        }
    }

    // Near-tie rescue: bit-exact emulation of the reference arithmetic (H1).
    if (best2 - best < 1e-3f) {
        int lo = bidx < bidx2 ? bidx : bidx2;
        int hi = bidx < bidx2 ? bidx2 : bidx;

        float lane0 = 0.f, lane1 = 0.f, lane2 = 0.f, lane3 = 0.f;
        float Blo = 0.f, Bhi = 0.f, dotlo = 0.f, dothi = 0.f;
        #pragma unroll 4
        for (int i = 0; i < 32; i++) {
            unsigned long long p = xr[i];
            float x0 = __uint_as_float((unsigned)p);          // d = 2i
            float x1 = __uint_as_float((unsigned)(p >> 32));  // d = 2i+1
            int d = 2 * i;
            // A lanes: lane (d&3), sequential in d within each lane
            if ((d & 2) == 0) { lane0 = fmaf(x0, x0, lane0); lane1 = fmaf(x1, x1, lane1); }
            else              { lane2 = fmaf(x0, x0, lane2); lane3 = fmaf(x1, x1, lane3); }
            float el0 = g_embT[lo * D + d],     eh0 = g_embT[hi * D + d];
            float el1 = g_embT[lo * D + d + 1], eh1 = g_embT[hi * D + d + 1];
            Blo   = fmaf(el1, el1, fmaf(el0, el0, Blo));
            Bhi   = fmaf(eh1, eh1, fmaf(eh0, eh0, Bhi));
            dotlo = fmaf(x1, el1, fmaf(x0, el0, dotlo));
            dothi = fmaf(x1, eh1, fmaf(x0, eh0, dothi));
        }
        float A = (lane0 + lane1) + (lane2 + lane3);
        // 2*dot is exact (power-of-two scale), so the final subtract rounds once
        // either way (fma contraction is rounding-identical here).
        float slo = A + Blo;   // fl(A + B_lo)
        float shi = A + Bhi;   // fl(A + B_hi)
        float distlo = slo - 2.0f * dotlo;
        float disthi = shi - 2.0f * dothi;
        bidx = (disthi < distlo) ? hi : lo;   // strict '<': ties -> lower index
    }
    g_idx[row] = bidx;
}

// Gather quantized codes (coalesced via g_embT), straight-through output
// out = x + (q - x) exactly as the reference computes it, and accumulate
// sum((q - x)^2) in double.
__global__ void vq_gather_kernel(const float* __restrict__ x, float* __restrict__ out) {
    __shared__ double sred[8];
    const long total = (long)NROWS * D / 4;
    double local = 0.0;
    for (long j = (long)blockIdx.x * blockDim.x + threadIdx.x; j < total;
         j += (long)gridDim.x * blockDim.x) {
        long i = j * 4;
        int row = (int)(i >> 6);
        int d   = (int)(i & 63);
        int idx = g_idx[row];
        float4 q  = *reinterpret_cast<const float4*>(&g_embT[idx * D + d]);
        float4 xv = *reinterpret_cast<const float4*>(x + i);
        float d0 = q.x - xv.x, d1 = q.y - xv.y, d2 = q.z - xv.z, d3 = q.w - xv.w;
        float4 o;
        o.x = xv.x + d0; o.y = xv.y + d1; o.z = xv.z + d2; o.w = xv.w + d3;
        *reinterpret_cast<float4*>(out + i) = o;
        local += (double)d0 * d0 + (double)d1 * d1 + (double)d2 * d2 + (double)d3 * d3;
    }
    #pragma unroll
    for (int off = 16; off > 0; off >>= 1)
        local += __shfl_down_sync(0xffffffffu, local, off);
    int wid = threadIdx.x >> 5, lid = threadIdx.x & 31;
    if (lid == 0) sred[wid] = local;
    __syncthreads();
    if (threadIdx.x == 0) {
        double s = 0.0;
        #pragma unroll
        for (int w = 0; w < 8; w++) s += sred[w];
        atomicAdd(&g_acc, s);
    }
}

__global__ void vq_finalize_kernel(float* __restrict__ loss_out) {
    double m = g_acc / (double)((long)NROWS * D);
    float lf = (float)m;
    // loss = BETA * commitment + codebook, both equal mean((q-x)^2) in value
    *loss_out = 0.25f * lf + lf;
}

extern "C" void kernel_launch(void* const* d_in, const int* in_sizes, int n_in,
                              void* d_out, int out_size) {
    const float* x   = (const float*)d_in[0];   // [256,32,32,64] fp32
    const float* emb = (const float*)d_in[1];   // [64,1024] fp32
    float* out = (float*)d_out;

    vq_init_kernel<<<256, 256>>>(emb);
    vq_argmin_kernel<<<NROWS / 256, 256>>>(x);
    vq_gather_kernel<<<2048, 256>>>(x, out);
    vq_finalize_kernel<<<1, 1>>>(out + (out_size - 1));
}